// round 8
// baseline (speedup 1.0000x reference)
#include <cuda_runtime.h>
#include <cuda_bf16.h>
#include <math.h>
#include <stdint.h>

// ---------------- problem constants ----------------
#define B_ROWS   16384
#define IN_DIM   2048
#define N_NODES  1023
#define NODE_PAD 1024
#define N_LEAVES 1024
#define OUT_DIM  512
#define DEPTH    10

// ---------------- device scratch (no allocations allowed) ----------------
__device__ float         g_P [(size_t)B_ROWS * NODE_PAD];     // fp32 node probs
__device__ __nv_bfloat16 g_xh[(size_t)B_ROWS * IN_DIM];
__device__ __nv_bfloat16 g_xl[(size_t)B_ROWS * IN_DIM];
__device__ __nv_bfloat16 g_wh[(size_t)NODE_PAD * IN_DIM];     // W^T split, [n][k]
__device__ __nv_bfloat16 g_wl[(size_t)NODE_PAD * IN_DIM];
__device__ __nv_bfloat16 g_vh[(size_t)OUT_DIM * N_LEAVES];    // value^T split, [n][k]
__device__ __nv_bfloat16 g_vl[(size_t)OUT_DIM * N_LEAVES];
__device__ __nv_bfloat16 g_ph[(size_t)B_ROWS * N_LEAVES];     // leaf probs split
__device__ __nv_bfloat16 g_pl[(size_t)B_ROWS * N_LEAVES];
__device__ float         g_regpart[128 * NODE_PAD];

// ==========================================================================
// mma.sync bf16 helpers (sm_80-era PTX: valid on plain sm_103 target)
// ==========================================================================
__device__ __forceinline__ uint32_t smem_u32(const void* p) {
    uint32_t a;
    asm("{ .reg .u64 t; cvta.to.shared.u64 t, %1; cvt.u32.u64 %0, t; }" : "=r"(a) : "l"(p));
    return a;
}
#define LDSM_X4(r, a) \
    asm volatile("ldmatrix.sync.aligned.m8n8.x4.shared.b16 {%0,%1,%2,%3}, [%4];" \
        : "=r"((r)[0]), "=r"((r)[1]), "=r"((r)[2]), "=r"((r)[3]) : "r"(a))

__device__ __forceinline__ void mma_bf16(float c[4], const uint32_t a[4],
                                         uint32_t b0, uint32_t b1) {
    asm volatile(
        "mma.sync.aligned.m16n8k16.row.col.f32.bf16.bf16.f32 "
        "{%0,%1,%2,%3}, {%4,%5,%6,%7}, {%8,%9}, {%0,%1,%2,%3};"
        : "+f"(c[0]), "+f"(c[1]), "+f"(c[2]), "+f"(c[3])
        : "r"(a[0]), "r"(a[1]), "r"(a[2]), "r"(a[3]), "r"(b0), "r"(b1));
}
#define CP_ASYNC16(s, g) \
    asm volatile("cp.async.cg.shared.global [%0], [%1], 16;" :: "r"(s), "l"(g))
#define CP_COMMIT()  asm volatile("cp.async.commit_group;")
#define CP_WAIT0()   asm volatile("cp.async.wait_group 0;")

// ==========================================================================
// bf16-split tensor-core GEMM: C[M,N] = (Ah+Al)@(Bh+Bl)^T  (lo*lo dropped)
// A: [M][K] row-major bf16 (hi/lo).  B: [n][K] k-major bf16 (hi/lo).
// CTA tile 128x128, BK=32, 2-stage double buffer, ONE sync per k-tile,
// 8 warps (2x4), warp tile 64x32, product-major MMA order (16 independent
// accumulators between same-acc reuse -> no RAW stalls on tensor pipe).
// __launch_bounds__(256,2): 2 CTAs/SM (smem 2x81920 fits).
// EPI==0: sigmoid(acc + bias[n]) -> fp32 C ; EPI==1: plain fp32 store
// ==========================================================================
#define ROWH   40            // smem row length in halves (32 data + 8 pad)
#define ROWB   80            // smem row stride bytes
#define MATB   (128 * ROWB)  // one matrix tile (128 rows) = 10240 B
#define STAGEB (4 * MATB)    // Ah, Al, Bh, Bl per stage = 40960 B
#define NSTAGE 2
#define SMEM_DYN (NSTAGE * STAGEB)   // 81920 B

template <int EPI>
__global__ __launch_bounds__(256, 2)
void mma_gemm_kernel(const __nv_bfloat16* __restrict__ Ah,
                     const __nv_bfloat16* __restrict__ Al,
                     const __nv_bfloat16* __restrict__ Bh,
                     const __nv_bfloat16* __restrict__ Bl,
                     const float* __restrict__ bias,
                     float* __restrict__ Cout,
                     int K, int ldc, int Nvalid)
{
    extern __shared__ char smem[];
    const uint32_t sbase = smem_u32(smem);
    const int tid  = threadIdx.x;
    const int wid  = tid >> 5;
    const int lane = tid & 31;
    const int wm   = wid & 1;          // warp row  (2)  -> M 64
    const int wn   = wid >> 1;         // warp col  (4)  -> N 32

    const int row0 = blockIdx.y * 128;
    const int col0 = blockIdx.x * 128;

    const int T = K >> 5;              // k-tiles of 32

    // ---- cp.async mapping: 512 x 16B chunks per matrix, 2 per thread ----
    const int ch_r0  = tid >> 2;             // row of chunk 0   (0..63)
    const int ch_c0  = (tid & 3) << 3;       // half-offset 0/8/16/24
    const __nv_bfloat16* gA[2] = { Ah, Al };
    const __nv_bfloat16* gB[2] = { Bh, Bl };

    // ---- ldmatrix per-lane offsets ----
    const int laA = ((lane & 15) * ROWH + ((lane >> 4) << 3)) * 2;  // A tiles
    const int laB = (((lane & 7) + ((lane >> 4) << 3)) * ROWH + (((lane >> 3) & 1) << 3)) * 2;

    float c[4][4][4];
    #pragma unroll
    for (int i = 0; i < 4; ++i)
        #pragma unroll
        for (int j = 0; j < 4; ++j)
            #pragma unroll
            for (int r = 0; r < 4; ++r) c[i][j][r] = 0.f;

    // ---- stage loader ----
    auto load_stage = [&](int t, int s) {
        const uint32_t sb = sbase + s * STAGEB;
        const int kh = t * 32;                     // k offset in halves
        #pragma unroll
        for (int m = 0; m < 2; ++m) {              // Ah, Al
            const __nv_bfloat16* src = gA[m];
            #pragma unroll
            for (int j = 0; j < 2; ++j) {
                const int r = ch_r0 + j * 64;
                CP_ASYNC16(sb + m * MATB + r * ROWB + ch_c0 * 2,
                           src + (size_t)(row0 + r) * K + kh + ch_c0);
            }
        }
        #pragma unroll
        for (int m = 0; m < 2; ++m) {              // Bh, Bl
            const __nv_bfloat16* src = gB[m];
            #pragma unroll
            for (int j = 0; j < 2; ++j) {
                const int r = ch_r0 + j * 64;
                CP_ASYNC16(sb + (2 + m) * MATB + r * ROWB + ch_c0 * 2,
                           src + (size_t)(col0 + r) * K + kh + ch_c0);
            }
        }
    };

    // ---- prologue: stage 0 ----
    load_stage(0, 0); CP_COMMIT();

    for (int t = 0; t < T; ++t) {
        const int cur = t & 1;

        // stage t is the only outstanding group -> full drain waits just for it
        CP_WAIT0();
        __syncthreads();       // single barrier: data ready AND buffer cur^1 free

        // prefetch t+1 into the other buffer; lands during compute below
        if (t + 1 < T) { load_stage(t + 1, cur ^ 1); CP_COMMIT(); }

        const uint32_t sb = sbase + cur * STAGEB;
        const uint32_t aHu = sb,            aLu = sb + MATB;
        const uint32_t bHu = sb + 2 * MATB, bLu = sb + 3 * MATB;

        #pragma unroll
        for (int ks = 0; ks < 2; ++ks) {
            const int ko = ks * 32;   // bytes: 16 halves
            uint32_t ah[4][4], al[4][4], bh[2][4], bl[2][4];
            #pragma unroll
            for (int mi = 0; mi < 4; ++mi) {
                const uint32_t off = (wm * 64 + mi * 16) * ROWB + ko + laA;
                LDSM_X4(ah[mi], aHu + off);
                LDSM_X4(al[mi], aLu + off);
            }
            #pragma unroll
            for (int pr = 0; pr < 2; ++pr) {
                const uint32_t off = (wn * 32 + pr * 16) * ROWB + ko + laB;
                LDSM_X4(bh[pr], bHu + off);
                LDSM_X4(bl[pr], bLu + off);
            }
            // product-major order: 16 independent accumulators between
            // same-accumulator reuses -> no HMMA RAW chains
            #pragma unroll
            for (int mi = 0; mi < 4; ++mi)
                #pragma unroll
                for (int ni = 0; ni < 4; ++ni) {
                    const int pr = ni >> 1, ix = (ni & 1) << 1;
                    mma_bf16(c[mi][ni], ah[mi], bh[pr][ix], bh[pr][ix + 1]);
                }
            #pragma unroll
            for (int mi = 0; mi < 4; ++mi)
                #pragma unroll
                for (int ni = 0; ni < 4; ++ni) {
                    const int pr = ni >> 1, ix = (ni & 1) << 1;
                    mma_bf16(c[mi][ni], al[mi], bh[pr][ix], bh[pr][ix + 1]);
                }
            #pragma unroll
            for (int mi = 0; mi < 4; ++mi)
                #pragma unroll
                for (int ni = 0; ni < 4; ++ni) {
                    const int pr = ni >> 1, ix = (ni & 1) << 1;
                    mma_bf16(c[mi][ni], ah[mi], bl[pr][ix], bl[pr][ix + 1]);
                }
        }
    }

    // ---- epilogue ----
    const int er = lane >> 2;            // 0..7
    const int ec = (lane & 3) << 1;      // 0,2,4,6
    #pragma unroll
    for (int mi = 0; mi < 4; ++mi) {
        #pragma unroll
        for (int ni = 0; ni < 4; ++ni) {
            const int gr = row0 + wm * 64 + mi * 16 + er;
            const int gc = col0 + wn * 32 + ni * 8 + ec;
            #pragma unroll
            for (int h = 0; h < 2; ++h) {          // row gr, gr+8
                float v0 = c[mi][ni][h * 2 + 0];
                float v1 = c[mi][ni][h * 2 + 1];
                if (EPI == 0) {
                    const float b0 = (gc + 0 < Nvalid) ? bias[gc + 0] : 0.f;
                    const float b1 = (gc + 1 < Nvalid) ? bias[gc + 1] : 0.f;
                    v0 = 1.f / (1.f + __expf(-(v0 + b0)));
                    v1 = 1.f / (1.f + __expf(-(v1 + b1)));
                }
                float2 st; st.x = v0; st.y = v1;
                *(float2*)&Cout[(size_t)(gr + h * 8) * ldc + gc] = st;
            }
        }
    }
}

// ==========================================================================
// x -> (hi, lo) bf16 split, vectorized
// ==========================================================================
__global__ __launch_bounds__(256)
void xsplit_kernel(const float* __restrict__ x,
                   __nv_bfloat16* __restrict__ hi, __nv_bfloat16* __restrict__ lo)
{
    const size_t i4 = (size_t)blockIdx.x * 256 + threadIdx.x;   // float4 index
    const float4 v = ((const float4*)x)[i4];
    __nv_bfloat16 h0 = __float2bfloat16(v.x), h1 = __float2bfloat16(v.y);
    __nv_bfloat16 h2 = __float2bfloat16(v.z), h3 = __float2bfloat16(v.w);
    __nv_bfloat16 l0 = __float2bfloat16(v.x - __bfloat162float(h0));
    __nv_bfloat16 l1 = __float2bfloat16(v.y - __bfloat162float(h1));
    __nv_bfloat16 l2 = __float2bfloat16(v.z - __bfloat162float(h2));
    __nv_bfloat16 l3 = __float2bfloat16(v.w - __bfloat162float(h3));
    ((__nv_bfloat162*)hi)[i4 * 2 + 0] = __halves2bfloat162(h0, h1);
    ((__nv_bfloat162*)hi)[i4 * 2 + 1] = __halves2bfloat162(h2, h3);
    ((__nv_bfloat162*)lo)[i4 * 2 + 0] = __halves2bfloat162(l0, l1);
    ((__nv_bfloat162*)lo)[i4 * 2 + 1] = __halves2bfloat162(l2, l3);
}

// ==========================================================================
// transpose + split:  src[R][Cv] (row-major) -> hi/lo[Cpad][R] (k-major)
// ==========================================================================
__global__ __launch_bounds__(256)
void tsplit_kernel(const float* __restrict__ src,
                   __nv_bfloat16* __restrict__ hi, __nv_bfloat16* __restrict__ lo,
                   int R, int Cv)
{
    __shared__ float t[32][33];
    const int c0 = blockIdx.x * 32, r0 = blockIdx.y * 32;
    const int tx = threadIdx.x & 31, ty = threadIdx.x >> 5;
    #pragma unroll
    for (int i = 0; i < 4; ++i) {
        const int r = r0 + ty + i * 8, c = c0 + tx;
        t[ty + i * 8][tx] = (c < Cv) ? src[(size_t)r * Cv + c] : 0.f;
    }
    __syncthreads();
    #pragma unroll
    for (int i = 0; i < 4; ++i) {
        const int c = c0 + ty + i * 8, r = r0 + tx;
        const float f = t[tx][ty + i * 8];
        const __nv_bfloat16 h = __float2bfloat16(f);
        const __nv_bfloat16 l = __float2bfloat16(f - __bfloat162float(h));
        hi[(size_t)c * R + r] = h;
        lo[(size_t)c * R + r] = l;
    }
}

// ==========================================================================
// Tree expansion: leaf probs (fp32) -> bf16 hi/lo split
// ==========================================================================
__global__ __launch_bounds__(256)
void tree_kernel(const float* __restrict__ P,
                 __nv_bfloat16* __restrict__ ph, __nv_bfloat16* __restrict__ pl)
{
    __shared__ float sP[NODE_PAD];
    const int row = blockIdx.x;
    const float* Prow = P + (size_t)row * NODE_PAD;
    for (int i = threadIdx.x; i < N_NODES; i += 256) sP[i] = Prow[i];
    __syncthreads();

    for (int lf = threadIdx.x; lf < N_LEAVES; lf += 256) {
        float prod = 1.f;
        #pragma unroll
        for (int d = 0; d < DEPTH; ++d) {
            const int idx  = lf >> (DEPTH - d);
            const int node = (1 << d) - 1 + idx;
            const float p  = sP[node];
            const int bit  = (lf >> (DEPTH - 1 - d)) & 1;
            prod *= bit ? (1.f - p) : p;
        }
        const __nv_bfloat16 h = __float2bfloat16(prod);
        const __nv_bfloat16 l = __float2bfloat16(prod - __bfloat162float(h));
        ph[(size_t)row * N_LEAVES + lf] = h;
        pl[(size_t)row * N_LEAVES + lf] = l;
    }
}

// ==========================================================================
// Regularizer (deterministic two-stage)
// ==========================================================================
__global__ __launch_bounds__(256)
void reg_partial_kernel(const float* __restrict__ P, float* __restrict__ part)
{
    const int b  = blockIdx.x;
    const int c0 = threadIdx.x;
    float acc[4] = {0.f, 0.f, 0.f, 0.f};
    for (int r = 0; r < 128; ++r) {
        const float* Prow = P + (size_t)(b * 128 + r) * NODE_PAD;
        #pragma unroll
        for (int j = 0; j < 4; ++j) {
            const int c = c0 + j * 256;
            if (c < N_NODES) {
                const float p = Prow[c];
                acc[j] += __logf(fmaxf(p * (1.f - p), 1e-5f));
            }
        }
    }
    #pragma unroll
    for (int j = 0; j < 4; ++j) {
        const int c = c0 + j * 256;
        if (c < NODE_PAD) part[b * NODE_PAD + c] = (c < N_NODES) ? acc[j] : 0.f;
    }
}

__global__ __launch_bounds__(1024)
void reg_final_kernel(const float* __restrict__ part, float* __restrict__ out_reg)
{
    __shared__ float red[1024];
    const int c = threadIdx.x;
    float s = 0.f;
    if (c < N_NODES) {
        for (int i = 0; i < 128; ++i) s += part[i * NODE_PAD + c];
        const int d = 31 - __clz(c + 1);
        s = -0.5f * exp2f((float)(-d)) * (s / (float)B_ROWS);
    }
    red[c] = s;
    __syncthreads();
    #pragma unroll
    for (int st = 512; st > 0; st >>= 1) {
        if (c < st) red[c] += red[c + st];
        __syncthreads();
    }
    if (c == 0) *out_reg = red[0];
}

// ==========================================================================
extern "C" void kernel_launch(void* const* d_in, const int* in_sizes, int n_in,
                              void* d_out, int out_size)
{
    const float* x     = (const float*)d_in[0];   // [16384, 2048]
    const float* W     = (const float*)d_in[1];   // [2048, 1023]
    const float* bias  = (const float*)d_in[2];   // [1023]
    const float* value = (const float*)d_in[3];   // [1024, 512]
    float* out = (float*)d_out;

    float *P, *part;
    __nv_bfloat16 *xh, *xl, *wh, *wl, *vh, *vl, *ph, *pl;
    cudaGetSymbolAddress((void**)&P,  g_P);
    cudaGetSymbolAddress((void**)&part, g_regpart);
    cudaGetSymbolAddress((void**)&xh, g_xh);  cudaGetSymbolAddress((void**)&xl, g_xl);
    cudaGetSymbolAddress((void**)&wh, g_wh);  cudaGetSymbolAddress((void**)&wl, g_wl);
    cudaGetSymbolAddress((void**)&vh, g_vh);  cudaGetSymbolAddress((void**)&vl, g_vl);
    cudaGetSymbolAddress((void**)&ph, g_ph);  cudaGetSymbolAddress((void**)&pl, g_pl);

    cudaFuncSetAttribute(mma_gemm_kernel<0>, cudaFuncAttributeMaxDynamicSharedMemorySize, SMEM_DYN);
    cudaFuncSetAttribute(mma_gemm_kernel<1>, cudaFuncAttributeMaxDynamicSharedMemorySize, SMEM_DYN);

    // 1. operand splits
    xsplit_kernel<<<(B_ROWS * IN_DIM) / 1024, 256>>>(x, xh, xl);
    {   // W [2048,1023] -> wh/wl [1024][2048]
        dim3 g(NODE_PAD / 32, IN_DIM / 32);
        tsplit_kernel<<<g, 256>>>(W, wh, wl, IN_DIM, N_NODES);
    }
    {   // value [1024,512] -> vh/vl [512][1024]
        dim3 g(OUT_DIM / 32, N_LEAVES / 32);
        tsplit_kernel<<<g, 256>>>(value, vh, vl, N_LEAVES, OUT_DIM);
    }

    // 2. GEMM1: P = sigmoid(x@W + b)   M=16384, N=1024(pad), K=2048
    {
        dim3 grid(NODE_PAD / 128, B_ROWS / 128);   // (8, 128)
        mma_gemm_kernel<0><<<grid, 256, SMEM_DYN>>>(xh, xl, wh, wl, bias, P,
                                                    IN_DIM, NODE_PAD, N_NODES);
    }

    // 3. tree -> leaf probs (bf16 split)
    tree_kernel<<<B_ROWS, 256>>>(P, ph, pl);

    // 4. regularizer
    reg_partial_kernel<<<128, 256>>>(P, part);
    if (out_size > B_ROWS * OUT_DIM) {
        reg_final_kernel<<<1, 1024>>>(part, out + (out_size - 1));
    }

    // 5. GEMM2: out = probs @ value   M=16384, N=512, K=1024
    {
        dim3 grid(OUT_DIM / 128, B_ROWS / 128);    // (4, 128)
        mma_gemm_kernel<1><<<grid, 256, SMEM_DYN>>>(ph, pl, vh, vl, nullptr, out,
                                                    N_LEAVES, OUT_DIM, OUT_DIM);
    }
}

// round 11
// speedup vs baseline: 1.3073x; 1.3073x over previous
#include <cuda_runtime.h>
#include <cuda_fp16.h>
#include <math.h>
#include <stdint.h>

// ---------------- problem constants ----------------
#define B_ROWS   16384
#define IN_DIM   2048
#define N_NODES  1023
#define NODE_PAD 1024
#define N_LEAVES 1024
#define OUT_DIM  512
#define DEPTH    10

// ---------------- device scratch (no allocations allowed) ----------------
__device__ float  g_P [(size_t)B_ROWS * NODE_PAD];     // fp32 node probs
__device__ __half g_xh[(size_t)B_ROWS * IN_DIM];
__device__ __half g_xl[(size_t)B_ROWS * IN_DIM];
__device__ __half g_wh[(size_t)NODE_PAD * IN_DIM];     // W^T fp16, [n][k]
__device__ __half g_vh[(size_t)OUT_DIM * N_LEAVES];    // value^T fp16, [n][k]
__device__ __half g_ph[(size_t)B_ROWS * N_LEAVES];     // leaf probs hi
__device__ __half g_pl[(size_t)B_ROWS * N_LEAVES];     // leaf probs lo
__device__ float  g_regpart[128 * NODE_PAD];

// ==========================================================================
// mma.sync fp16 helpers (sm_80-era PTX: valid on plain sm_103 target)
// ==========================================================================
__device__ __forceinline__ uint32_t smem_u32(const void* p) {
    uint32_t a;
    asm("{ .reg .u64 t; cvta.to.shared.u64 t, %1; cvt.u32.u64 %0, t; }" : "=r"(a) : "l"(p));
    return a;
}
#define LDSM_X4(r, a) \
    asm volatile("ldmatrix.sync.aligned.m8n8.x4.shared.b16 {%0,%1,%2,%3}, [%4];" \
        : "=r"((r)[0]), "=r"((r)[1]), "=r"((r)[2]), "=r"((r)[3]) : "r"(a))

__device__ __forceinline__ void mma_f16(float c[4], const uint32_t a[4],
                                        uint32_t b0, uint32_t b1) {
    asm volatile(
        "mma.sync.aligned.m16n8k16.row.col.f32.f16.f16.f32 "
        "{%0,%1,%2,%3}, {%4,%5,%6,%7}, {%8,%9}, {%0,%1,%2,%3};"
        : "+f"(c[0]), "+f"(c[1]), "+f"(c[2]), "+f"(c[3])
        : "r"(a[0]), "r"(a[1]), "r"(a[2]), "r"(a[3]), "r"(b0), "r"(b1));
}
#define CP_ASYNC16(s, g) \
    asm volatile("cp.async.cg.shared.global [%0], [%1], 16;" :: "r"(s), "l"(g))
#define CP_COMMIT()  asm volatile("cp.async.commit_group;")
#define CP_WAIT0()   asm volatile("cp.async.wait_group 0;")

// ==========================================================================
// fp16 2-product tensor-core GEMM: C = (Ah+Al)@Bh^T
// A: [M][K] row-major fp16 hi/lo.  B: [n][K] k-major fp16 (hi only).
// CTA tile 128x128, BK=32, 2-stage double buffer, one sync per k-tile,
// 8 warps (2x4), warp tile 64x32, product-major MMA order.
// __launch_bounds__(256,2): 2 CTAs/SM (smem 2x61440 fits).
// EPI==0: sigmoid(acc + bias[n]) -> fp32 C ; EPI==1: plain fp32 store
// ==========================================================================
#define ROWH   40            // smem row length in halves (32 data + 8 pad)
#define ROWB   80            // smem row stride bytes
#define MATB   (128 * ROWB)  // one matrix tile (128 rows) = 10240 B
#define STAGEB (3 * MATB)    // Ah, Al, Bh per stage = 30720 B
#define NSTAGE 2
#define SMEM_DYN (NSTAGE * STAGEB)   // 61440 B

template <int EPI>
__global__ __launch_bounds__(256, 2)
void mma_gemm_kernel(const __half* __restrict__ Ah,
                     const __half* __restrict__ Al,
                     const __half* __restrict__ Bh,
                     const float* __restrict__ bias,
                     float* __restrict__ Cout,
                     int K, int ldc, int Nvalid)
{
    extern __shared__ char smem[];
    const uint32_t sbase = smem_u32(smem);
    const int tid  = threadIdx.x;
    const int wid  = tid >> 5;
    const int lane = tid & 31;
    const int wm   = wid & 1;          // warp row  (2)  -> M 64
    const int wn   = wid >> 1;         // warp col  (4)  -> N 32

    const int row0 = blockIdx.y * 128;
    const int col0 = blockIdx.x * 128;

    const int T = K >> 5;              // k-tiles of 32

    // ---- cp.async mapping: 512 x 16B chunks per matrix, 2 per thread ----
    const int ch_r0  = tid >> 2;             // row of chunk 0   (0..63)
    const int ch_c0  = (tid & 3) << 3;       // half-offset 0/8/16/24
    const __half* gA[2] = { Ah, Al };

    // ---- ldmatrix per-lane offsets ----
    const int laA = ((lane & 15) * ROWH + ((lane >> 4) << 3)) * 2;  // A tiles
    const int laB = (((lane & 7) + ((lane >> 4) << 3)) * ROWH + (((lane >> 3) & 1) << 3)) * 2;

    float c[4][4][4];
    #pragma unroll
    for (int i = 0; i < 4; ++i)
        #pragma unroll
        for (int j = 0; j < 4; ++j)
            #pragma unroll
            for (int r = 0; r < 4; ++r) c[i][j][r] = 0.f;

    // ---- stage loader: Ah, Al, Bh (3 matrices) ----
    auto load_stage = [&](int t, int s) {
        const uint32_t sb = sbase + s * STAGEB;
        const int kh = t * 32;                     // k offset in halves
        #pragma unroll
        for (int m = 0; m < 2; ++m) {              // Ah, Al
            const __half* src = gA[m];
            #pragma unroll
            for (int j = 0; j < 2; ++j) {
                const int r = ch_r0 + j * 64;
                CP_ASYNC16(sb + m * MATB + r * ROWB + ch_c0 * 2,
                           src + (size_t)(row0 + r) * K + kh + ch_c0);
            }
        }
        #pragma unroll
        for (int j = 0; j < 2; ++j) {              // Bh
            const int r = ch_r0 + j * 64;
            CP_ASYNC16(sb + 2 * MATB + r * ROWB + ch_c0 * 2,
                       Bh + (size_t)(col0 + r) * K + kh + ch_c0);
        }
    };

    // ---- prologue: stage 0 ----
    load_stage(0, 0); CP_COMMIT();

    for (int t = 0; t < T; ++t) {
        const int cur = t & 1;

        CP_WAIT0();
        __syncthreads();       // single barrier: data ready AND buffer cur^1 free

        if (t + 1 < T) { load_stage(t + 1, cur ^ 1); CP_COMMIT(); }

        const uint32_t sb = sbase + cur * STAGEB;
        const uint32_t aHu = sb, aLu = sb + MATB, bHu = sb + 2 * MATB;

        #pragma unroll
        for (int ks = 0; ks < 2; ++ks) {
            const int ko = ks * 32;   // bytes: 16 halves
            uint32_t ah[4][4], al[4][4], bh[2][4];
            #pragma unroll
            for (int mi = 0; mi < 4; ++mi) {
                const uint32_t off = (wm * 64 + mi * 16) * ROWB + ko + laA;
                LDSM_X4(ah[mi], aHu + off);
                LDSM_X4(al[mi], aLu + off);
            }
            #pragma unroll
            for (int pr = 0; pr < 2; ++pr) {
                const uint32_t off = (wn * 32 + pr * 16) * ROWB + ko + laB;
                LDSM_X4(bh[pr], bHu + off);
            }
            // 2 products, product-major (independent accumulators between reuse)
            #pragma unroll
            for (int mi = 0; mi < 4; ++mi)
                #pragma unroll
                for (int ni = 0; ni < 4; ++ni) {
                    const int pr = ni >> 1, ix = (ni & 1) << 1;
                    mma_f16(c[mi][ni], ah[mi], bh[pr][ix], bh[pr][ix + 1]);
                }
            #pragma unroll
            for (int mi = 0; mi < 4; ++mi)
                #pragma unroll
                for (int ni = 0; ni < 4; ++ni) {
                    const int pr = ni >> 1, ix = (ni & 1) << 1;
                    mma_f16(c[mi][ni], al[mi], bh[pr][ix], bh[pr][ix + 1]);
                }
        }
    }

    // ---- epilogue ----
    const int er = lane >> 2;            // 0..7
    const int ec = (lane & 3) << 1;      // 0,2,4,6
    #pragma unroll
    for (int mi = 0; mi < 4; ++mi) {
        #pragma unroll
        for (int ni = 0; ni < 4; ++ni) {
            const int gr = row0 + wm * 64 + mi * 16 + er;
            const int gc = col0 + wn * 32 + ni * 8 + ec;
            #pragma unroll
            for (int h = 0; h < 2; ++h) {          // row gr, gr+8
                float v0 = c[mi][ni][h * 2 + 0];
                float v1 = c[mi][ni][h * 2 + 1];
                if (EPI == 0) {
                    const float b0 = (gc + 0 < Nvalid) ? bias[gc + 0] : 0.f;
                    const float b1 = (gc + 1 < Nvalid) ? bias[gc + 1] : 0.f;
                    v0 = 1.f / (1.f + __expf(-(v0 + b0)));
                    v1 = 1.f / (1.f + __expf(-(v1 + b1)));
                }
                float2 st; st.x = v0; st.y = v1;
                *(float2*)&Cout[(size_t)(gr + h * 8) * ldc + gc] = st;
            }
        }
    }
}

// ==========================================================================
// x -> (hi, lo) fp16 split, vectorized  (22 effective mantissa bits)
// ==========================================================================
__global__ __launch_bounds__(256)
void xsplit_kernel(const float* __restrict__ x,
                   __half* __restrict__ hi, __half* __restrict__ lo)
{
    const size_t i4 = (size_t)blockIdx.x * 256 + threadIdx.x;   // float4 index
    const float4 v = ((const float4*)x)[i4];
    __half h0 = __float2half(v.x), h1 = __float2half(v.y);
    __half h2 = __float2half(v.z), h3 = __float2half(v.w);
    __half l0 = __float2half(v.x - __half2float(h0));
    __half l1 = __float2half(v.y - __half2float(h1));
    __half l2 = __float2half(v.z - __half2float(h2));
    __half l3 = __float2half(v.w - __half2float(h3));
    ((__half2*)hi)[i4 * 2 + 0] = __halves2half2(h0, h1);
    ((__half2*)hi)[i4 * 2 + 1] = __halves2half2(h2, h3);
    ((__half2*)lo)[i4 * 2 + 0] = __halves2half2(l0, l1);
    ((__half2*)lo)[i4 * 2 + 1] = __halves2half2(l2, l3);
}

// ==========================================================================
// transpose + fp16 convert:  src[R][Cv] (row-major) -> hi[Cpad][R] (k-major)
// ==========================================================================
__global__ __launch_bounds__(256)
void tsplit_kernel(const float* __restrict__ src,
                   __half* __restrict__ hi,
                   int R, int Cv)
{
    __shared__ float t[32][33];
    const int c0 = blockIdx.x * 32, r0 = blockIdx.y * 32;
    const int tx = threadIdx.x & 31, ty = threadIdx.x >> 5;
    #pragma unroll
    for (int i = 0; i < 4; ++i) {
        const int r = r0 + ty + i * 8, c = c0 + tx;
        t[ty + i * 8][tx] = (c < Cv) ? src[(size_t)r * Cv + c] : 0.f;
    }
    __syncthreads();
    #pragma unroll
    for (int i = 0; i < 4; ++i) {
        const int c = c0 + ty + i * 8, r = r0 + tx;
        hi[(size_t)c * R + r] = __float2half(t[tx][ty + i * 8]);
    }
}

// ==========================================================================
// Tree expansion: leaf probs (fp32) -> fp16 hi/lo split
// ==========================================================================
__global__ __launch_bounds__(256)
void tree_kernel(const float* __restrict__ P,
                 __half* __restrict__ ph, __half* __restrict__ pl)
{
    __shared__ float sP[NODE_PAD];
    const int row = blockIdx.x;
    const float* Prow = P + (size_t)row * NODE_PAD;
    for (int i = threadIdx.x; i < N_NODES; i += 256) sP[i] = Prow[i];
    __syncthreads();

    for (int lf = threadIdx.x; lf < N_LEAVES; lf += 256) {
        float prod = 1.f;
        #pragma unroll
        for (int d = 0; d < DEPTH; ++d) {
            const int idx  = lf >> (DEPTH - d);
            const int node = (1 << d) - 1 + idx;
            const float p  = sP[node];
            const int bit  = (lf >> (DEPTH - 1 - d)) & 1;
            prod *= bit ? (1.f - p) : p;
        }
        const __half h = __float2half(prod);
        const __half l = __float2half(prod - __half2float(h));
        ph[(size_t)row * N_LEAVES + lf] = h;
        pl[(size_t)row * N_LEAVES + lf] = l;
    }
}

// ==========================================================================
// Regularizer (deterministic two-stage)
// ==========================================================================
__global__ __launch_bounds__(256)
void reg_partial_kernel(const float* __restrict__ P, float* __restrict__ part)
{
    const int b  = blockIdx.x;
    const int c0 = threadIdx.x;
    float acc[4] = {0.f, 0.f, 0.f, 0.f};
    for (int r = 0; r < 128; ++r) {
        const float* Prow = P + (size_t)(b * 128 + r) * NODE_PAD;
        #pragma unroll
        for (int j = 0; j < 4; ++j) {
            const int c = c0 + j * 256;
            if (c < N_NODES) {
                const float p = Prow[c];
                acc[j] += __logf(fmaxf(p * (1.f - p), 1e-5f));
            }
        }
    }
    #pragma unroll
    for (int j = 0; j < 4; ++j) {
        const int c = c0 + j * 256;
        if (c < NODE_PAD) part[b * NODE_PAD + c] = (c < N_NODES) ? acc[j] : 0.f;
    }
}

__global__ __launch_bounds__(1024)
void reg_final_kernel(const float* __restrict__ part, float* __restrict__ out_reg)
{
    __shared__ float red[1024];
    const int c = threadIdx.x;
    float s = 0.f;
    if (c < N_NODES) {
        for (int i = 0; i < 128; ++i) s += part[i * NODE_PAD + c];
        const int d = 31 - __clz(c + 1);
        s = -0.5f * exp2f((float)(-d)) * (s / (float)B_ROWS);
    }
    red[c] = s;
    __syncthreads();
    #pragma unroll
    for (int st = 512; st > 0; st >>= 1) {
        if (c < st) red[c] += red[c + st];
        __syncthreads();
    }
    if (c == 0) *out_reg = red[0];
}

// ==========================================================================
extern "C" void kernel_launch(void* const* d_in, const int* in_sizes, int n_in,
                              void* d_out, int out_size)
{
    const float* x     = (const float*)d_in[0];   // [16384, 2048]
    const float* W     = (const float*)d_in[1];   // [2048, 1023]
    const float* bias  = (const float*)d_in[2];   // [1023]
    const float* value = (const float*)d_in[3];   // [1024, 512]
    float* out = (float*)d_out;

    float *P, *part;
    __half *xh, *xl, *wh, *vh, *ph, *pl;
    cudaGetSymbolAddress((void**)&P,  g_P);
    cudaGetSymbolAddress((void**)&part, g_regpart);
    cudaGetSymbolAddress((void**)&xh, g_xh);  cudaGetSymbolAddress((void**)&xl, g_xl);
    cudaGetSymbolAddress((void**)&wh, g_wh);
    cudaGetSymbolAddress((void**)&vh, g_vh);
    cudaGetSymbolAddress((void**)&ph, g_ph);  cudaGetSymbolAddress((void**)&pl, g_pl);

    cudaFuncSetAttribute(mma_gemm_kernel<0>, cudaFuncAttributeMaxDynamicSharedMemorySize, SMEM_DYN);
    cudaFuncSetAttribute(mma_gemm_kernel<1>, cudaFuncAttributeMaxDynamicSharedMemorySize, SMEM_DYN);

    // 1. operand splits / converts
    xsplit_kernel<<<(B_ROWS * IN_DIM) / 1024, 256>>>(x, xh, xl);
    {   // W [2048,1023] -> wh [1024][2048]
        dim3 g(NODE_PAD / 32, IN_DIM / 32);
        tsplit_kernel<<<g, 256>>>(W, wh, IN_DIM, N_NODES);
    }
    {   // value [1024,512] -> vh [512][1024]
        dim3 g(OUT_DIM / 32, N_LEAVES / 32);
        tsplit_kernel<<<g, 256>>>(value, vh, N_LEAVES, OUT_DIM);
    }

    // 2. GEMM1: P = sigmoid(x@W + b)   M=16384, N=1024(pad), K=2048
    {
        dim3 grid(NODE_PAD / 128, B_ROWS / 128);   // (8, 128)
        mma_gemm_kernel<0><<<grid, 256, SMEM_DYN>>>(xh, xl, wh, bias, P,
                                                    IN_DIM, NODE_PAD, N_NODES);
    }

    // 3. tree -> leaf probs (fp16 split)
    tree_kernel<<<B_ROWS, 256>>>(P, ph, pl);

    // 4. regularizer
    reg_partial_kernel<<<128, 256>>>(P, part);
    if (out_size > B_ROWS * OUT_DIM) {
        reg_final_kernel<<<1, 1024>>>(part, out + (out_size - 1));
    }

    // 5. GEMM2: out = probs @ value   M=16384, N=512, K=1024
    {
        dim3 grid(OUT_DIM / 128, B_ROWS / 128);    // (4, 128)
        mma_gemm_kernel<1><<<grid, 256, SMEM_DYN>>>(ph, pl, vh, nullptr, out,
                                                    N_LEAVES, OUT_DIM, OUT_DIM);
    }
}

// round 12
// speedup vs baseline: 1.9813x; 1.5155x over previous
#include <cuda_runtime.h>
#include <cuda_fp16.h>
#include <math.h>
#include <stdint.h>

// ---------------- problem constants ----------------
#define B_ROWS   16384
#define IN_DIM   2048
#define N_NODES  1023
#define NODE_PAD 1024
#define N_LEAVES 1024
#define OUT_DIM  512
#define DEPTH    10

// ---------------- device scratch (no allocations allowed) ----------------
__device__ float  g_P [(size_t)B_ROWS * NODE_PAD];     // fp32 node probs
__device__ __half g_xh[(size_t)B_ROWS * IN_DIM];       // x fp16
__device__ __half g_wh[(size_t)NODE_PAD * IN_DIM];     // W^T fp16, [n][k]
__device__ __half g_vh[(size_t)OUT_DIM * N_LEAVES];    // value^T fp16, [n][k]
__device__ __half g_ph[(size_t)B_ROWS * N_LEAVES];     // leaf probs fp16
__device__ float  g_regpart[128 * NODE_PAD];

// ==========================================================================
// mma.sync fp16 helpers (sm_80-era PTX: valid on plain sm_103 target)
// ==========================================================================
__device__ __forceinline__ uint32_t smem_u32(const void* p) {
    uint32_t a;
    asm("{ .reg .u64 t; cvta.to.shared.u64 t, %1; cvt.u32.u64 %0, t; }" : "=r"(a) : "l"(p));
    return a;
}
#define LDSM_X4(r, a) \
    asm volatile("ldmatrix.sync.aligned.m8n8.x4.shared.b16 {%0,%1,%2,%3}, [%4];" \
        : "=r"((r)[0]), "=r"((r)[1]), "=r"((r)[2]), "=r"((r)[3]) : "r"(a))

__device__ __forceinline__ void mma_f16(float c[4], const uint32_t a[4],
                                        uint32_t b0, uint32_t b1) {
    asm volatile(
        "mma.sync.aligned.m16n8k16.row.col.f32.f16.f16.f32 "
        "{%0,%1,%2,%3}, {%4,%5,%6,%7}, {%8,%9}, {%0,%1,%2,%3};"
        : "+f"(c[0]), "+f"(c[1]), "+f"(c[2]), "+f"(c[3])
        : "r"(a[0]), "r"(a[1]), "r"(a[2]), "r"(a[3]), "r"(b0), "r"(b1));
}
#define CP_ASYNC16(s, g) \
    asm volatile("cp.async.cg.shared.global [%0], [%1], 16;" :: "r"(s), "l"(g))
#define CP_COMMIT()  asm volatile("cp.async.commit_group;")
#define CP_WAIT0()   asm volatile("cp.async.wait_group 0;")

// ==========================================================================
// fp16 single-product tensor-core GEMM: C = A@B^T
// A: [M][K] row-major fp16.  B: [n][K] k-major fp16.
// CTA tile 128x128, BK=32, 2-stage double buffer, one sync per k-tile,
// 8 warps (2x4), warp tile 64x32.
// __launch_bounds__(256,2): 2 CTAs/SM.
// EPI==0: sigmoid(acc + bias[n]) -> fp32 C ; EPI==1: plain fp32 store
// ==========================================================================
#define ROWH   40            // smem row length in halves (32 data + 8 pad)
#define ROWB   80            // smem row stride bytes
#define MATB   (128 * ROWB)  // one matrix tile (128 rows) = 10240 B
#define STAGEB (2 * MATB)    // A, B per stage = 20480 B
#define NSTAGE 2
#define SMEM_DYN (NSTAGE * STAGEB)   // 40960 B

template <int EPI>
__global__ __launch_bounds__(256, 2)
void mma_gemm_kernel(const __half* __restrict__ Amat,
                     const __half* __restrict__ Bmat,
                     const float* __restrict__ bias,
                     float* __restrict__ Cout,
                     int K, int ldc, int Nvalid)
{
    extern __shared__ char smem[];
    const uint32_t sbase = smem_u32(smem);
    const int tid  = threadIdx.x;
    const int wid  = tid >> 5;
    const int lane = tid & 31;
    const int wm   = wid & 1;          // warp row  (2)  -> M 64
    const int wn   = wid >> 1;         // warp col  (4)  -> N 32

    const int row0 = blockIdx.y * 128;
    const int col0 = blockIdx.x * 128;

    const int T = K >> 5;              // k-tiles of 32

    // ---- cp.async mapping: 512 x 16B chunks per matrix, 2 per thread ----
    const int ch_r0  = tid >> 2;             // row of chunk 0   (0..63)
    const int ch_c0  = (tid & 3) << 3;       // half-offset 0/8/16/24

    // ---- ldmatrix per-lane offsets ----
    const int laA = ((lane & 15) * ROWH + ((lane >> 4) << 3)) * 2;  // A tiles
    const int laB = (((lane & 7) + ((lane >> 4) << 3)) * ROWH + (((lane >> 3) & 1) << 3)) * 2;

    float c[4][4][4];
    #pragma unroll
    for (int i = 0; i < 4; ++i)
        #pragma unroll
        for (int j = 0; j < 4; ++j)
            #pragma unroll
            for (int r = 0; r < 4; ++r) c[i][j][r] = 0.f;

    // ---- stage loader: A, B (2 matrices) ----
    auto load_stage = [&](int t, int s) {
        const uint32_t sb = sbase + s * STAGEB;
        const int kh = t * 32;                     // k offset in halves
        #pragma unroll
        for (int j = 0; j < 2; ++j) {              // A
            const int r = ch_r0 + j * 64;
            CP_ASYNC16(sb + r * ROWB + ch_c0 * 2,
                       Amat + (size_t)(row0 + r) * K + kh + ch_c0);
        }
        #pragma unroll
        for (int j = 0; j < 2; ++j) {              // B
            const int r = ch_r0 + j * 64;
            CP_ASYNC16(sb + MATB + r * ROWB + ch_c0 * 2,
                       Bmat + (size_t)(col0 + r) * K + kh + ch_c0);
        }
    };

    // ---- prologue: stage 0 ----
    load_stage(0, 0); CP_COMMIT();

    for (int t = 0; t < T; ++t) {
        const int cur = t & 1;

        CP_WAIT0();
        __syncthreads();       // single barrier: data ready AND buffer cur^1 free

        if (t + 1 < T) { load_stage(t + 1, cur ^ 1); CP_COMMIT(); }

        const uint32_t sb  = sbase + cur * STAGEB;
        const uint32_t aU  = sb;
        const uint32_t bU  = sb + MATB;

        #pragma unroll
        for (int ks = 0; ks < 2; ++ks) {
            const int ko = ks * 32;   // bytes: 16 halves
            uint32_t ah[4][4], bh[2][4];
            #pragma unroll
            for (int mi = 0; mi < 4; ++mi) {
                const uint32_t off = (wm * 64 + mi * 16) * ROWB + ko + laA;
                LDSM_X4(ah[mi], aU + off);
            }
            #pragma unroll
            for (int pr = 0; pr < 2; ++pr) {
                const uint32_t off = (wn * 32 + pr * 16) * ROWB + ko + laB;
                LDSM_X4(bh[pr], bU + off);
            }
            #pragma unroll
            for (int mi = 0; mi < 4; ++mi)
                #pragma unroll
                for (int ni = 0; ni < 4; ++ni) {
                    const int pr = ni >> 1, ix = (ni & 1) << 1;
                    mma_f16(c[mi][ni], ah[mi], bh[pr][ix], bh[pr][ix + 1]);
                }
        }
    }

    // ---- epilogue ----
    const int er = lane >> 2;            // 0..7
    const int ec = (lane & 3) << 1;      // 0,2,4,6
    #pragma unroll
    for (int mi = 0; mi < 4; ++mi) {
        #pragma unroll
        for (int ni = 0; ni < 4; ++ni) {
            const int gr = row0 + wm * 64 + mi * 16 + er;
            const int gc = col0 + wn * 32 + ni * 8 + ec;
            #pragma unroll
            for (int h = 0; h < 2; ++h) {          // row gr, gr+8
                float v0 = c[mi][ni][h * 2 + 0];
                float v1 = c[mi][ni][h * 2 + 1];
                if (EPI == 0) {
                    const float b0 = (gc + 0 < Nvalid) ? bias[gc + 0] : 0.f;
                    const float b1 = (gc + 1 < Nvalid) ? bias[gc + 1] : 0.f;
                    v0 = 1.f / (1.f + __expf(-(v0 + b0)));
                    v1 = 1.f / (1.f + __expf(-(v1 + b1)));
                }
                float2 st; st.x = v0; st.y = v1;
                *(float2*)&Cout[(size_t)(gr + h * 8) * ldc + gc] = st;
            }
        }
    }
}

// ==========================================================================
// x -> fp16 convert, vectorized
// ==========================================================================
__global__ __launch_bounds__(256)
void xconvert_kernel(const float* __restrict__ x, __half* __restrict__ hi)
{
    const size_t i4 = (size_t)blockIdx.x * 256 + threadIdx.x;   // float4 index
    const float4 v = ((const float4*)x)[i4];
    ((__half2*)hi)[i4 * 2 + 0] = __halves2half2(__float2half(v.x), __float2half(v.y));
    ((__half2*)hi)[i4 * 2 + 1] = __halves2half2(__float2half(v.z), __float2half(v.w));
}

// ==========================================================================
// transpose + fp16 convert:  src[R][Cv] (row-major) -> hi[Cpad][R] (k-major)
// ==========================================================================
__global__ __launch_bounds__(256)
void tsplit_kernel(const float* __restrict__ src,
                   __half* __restrict__ hi,
                   int R, int Cv)
{
    __shared__ float t[32][33];
    const int c0 = blockIdx.x * 32, r0 = blockIdx.y * 32;
    const int tx = threadIdx.x & 31, ty = threadIdx.x >> 5;
    #pragma unroll
    for (int i = 0; i < 4; ++i) {
        const int r = r0 + ty + i * 8, c = c0 + tx;
        t[ty + i * 8][tx] = (c < Cv) ? src[(size_t)r * Cv + c] : 0.f;
    }
    __syncthreads();
    #pragma unroll
    for (int i = 0; i < 4; ++i) {
        const int c = c0 + ty + i * 8, r = r0 + tx;
        hi[(size_t)c * R + r] = __float2half(t[tx][ty + i * 8]);
    }
}

// ==========================================================================
// Tree expansion: leaf probs (fp32 product) -> fp16
// ==========================================================================
__global__ __launch_bounds__(256)
void tree_kernel(const float* __restrict__ P, __half* __restrict__ ph)
{
    __shared__ float sP[NODE_PAD];
    const int row = blockIdx.x;
    const float* Prow = P + (size_t)row * NODE_PAD;
    for (int i = threadIdx.x; i < N_NODES; i += 256) sP[i] = Prow[i];
    __syncthreads();

    for (int lf = threadIdx.x; lf < N_LEAVES; lf += 256) {
        float prod = 1.f;
        #pragma unroll
        for (int d = 0; d < DEPTH; ++d) {
            const int idx  = lf >> (DEPTH - d);
            const int node = (1 << d) - 1 + idx;
            const float p  = sP[node];
            const int bit  = (lf >> (DEPTH - 1 - d)) & 1;
            prod *= bit ? (1.f - p) : p;
        }
        ph[(size_t)row * N_LEAVES + lf] = __float2half(prod);
    }
}

// ==========================================================================
// Regularizer (deterministic two-stage)
// ==========================================================================
__global__ __launch_bounds__(256)
void reg_partial_kernel(const float* __restrict__ P, float* __restrict__ part)
{
    const int b  = blockIdx.x;
    const int c0 = threadIdx.x;
    float acc[4] = {0.f, 0.f, 0.f, 0.f};
    for (int r = 0; r < 128; ++r) {
        const float* Prow = P + (size_t)(b * 128 + r) * NODE_PAD;
        #pragma unroll
        for (int j = 0; j < 4; ++j) {
            const int c = c0 + j * 256;
            if (c < N_NODES) {
                const float p = Prow[c];
                acc[j] += __logf(fmaxf(p * (1.f - p), 1e-5f));
            }
        }
    }
    #pragma unroll
    for (int j = 0; j < 4; ++j) {
        const int c = c0 + j * 256;
        if (c < NODE_PAD) part[b * NODE_PAD + c] = (c < N_NODES) ? acc[j] : 0.f;
    }
}

__global__ __launch_bounds__(1024)
void reg_final_kernel(const float* __restrict__ part, float* __restrict__ out_reg)
{
    __shared__ float red[1024];
    const int c = threadIdx.x;
    float s = 0.f;
    if (c < N_NODES) {
        for (int i = 0; i < 128; ++i) s += part[i * NODE_PAD + c];
        const int d = 31 - __clz(c + 1);
        s = -0.5f * exp2f((float)(-d)) * (s / (float)B_ROWS);
    }
    red[c] = s;
    __syncthreads();
    #pragma unroll
    for (int st = 512; st > 0; st >>= 1) {
        if (c < st) red[c] += red[c + st];
        __syncthreads();
    }
    if (c == 0) *out_reg = red[0];
}

// ==========================================================================
extern "C" void kernel_launch(void* const* d_in, const int* in_sizes, int n_in,
                              void* d_out, int out_size)
{
    const float* x     = (const float*)d_in[0];   // [16384, 2048]
    const float* W     = (const float*)d_in[1];   // [2048, 1023]
    const float* bias  = (const float*)d_in[2];   // [1023]
    const float* value = (const float*)d_in[3];   // [1024, 512]
    float* out = (float*)d_out;

    float *P, *part;
    __half *xh, *wh, *vh, *ph;
    cudaGetSymbolAddress((void**)&P,  g_P);
    cudaGetSymbolAddress((void**)&part, g_regpart);
    cudaGetSymbolAddress((void**)&xh, g_xh);
    cudaGetSymbolAddress((void**)&wh, g_wh);
    cudaGetSymbolAddress((void**)&vh, g_vh);
    cudaGetSymbolAddress((void**)&ph, g_ph);

    cudaFuncSetAttribute(mma_gemm_kernel<0>, cudaFuncAttributeMaxDynamicSharedMemorySize, SMEM_DYN);
    cudaFuncSetAttribute(mma_gemm_kernel<1>, cudaFuncAttributeMaxDynamicSharedMemorySize, SMEM_DYN);

    // 1. operand converts
    xconvert_kernel<<<(B_ROWS * IN_DIM) / 1024, 256>>>(x, xh);
    {   // W [2048,1023] -> wh [1024][2048]
        dim3 g(NODE_PAD / 32, IN_DIM / 32);
        tsplit_kernel<<<g, 256>>>(W, wh, IN_DIM, N_NODES);
    }
    {   // value [1024,512] -> vh [512][1024]
        dim3 g(OUT_DIM / 32, N_LEAVES / 32);
        tsplit_kernel<<<g, 256>>>(value, vh, N_LEAVES, OUT_DIM);
    }

    // 2. GEMM1: P = sigmoid(x@W + b)   M=16384, N=1024(pad), K=2048
    {
        dim3 grid(NODE_PAD / 128, B_ROWS / 128);   // (8, 128)
        mma_gemm_kernel<0><<<grid, 256, SMEM_DYN>>>(xh, wh, bias, P,
                                                    IN_DIM, NODE_PAD, N_NODES);
    }

    // 3. tree -> leaf probs (fp16)
    tree_kernel<<<B_ROWS, 256>>>(P, ph);

    // 4. regularizer
    reg_partial_kernel<<<128, 256>>>(P, part);
    if (out_size > B_ROWS * OUT_DIM) {
        reg_final_kernel<<<1, 1024>>>(part, out + (out_size - 1));
    }

    // 5. GEMM2: out = probs @ value   M=16384, N=512, K=1024
    {
        dim3 grid(OUT_DIM / 128, B_ROWS / 128);    // (4, 128)
        mma_gemm_kernel<1><<<grid, 256, SMEM_DYN>>>(ph, vh, nullptr, out,
                                                    N_LEAVES, OUT_DIM, OUT_DIM);
    }
}

// round 13
// speedup vs baseline: 2.1177x; 1.0688x over previous
#include <cuda_runtime.h>
#include <cuda_fp16.h>
#include <math.h>
#include <stdint.h>

// ---------------- problem constants ----------------
#define B_ROWS   16384
#define IN_DIM   2048
#define N_NODES  1023
#define NODE_PAD 1024
#define N_LEAVES 1024
#define OUT_DIM  512
#define DEPTH    10

// ---------------- device scratch (no allocations allowed) ----------------
__device__ float  g_P [(size_t)B_ROWS * NODE_PAD];     // fp32 node probs
__device__ __half g_xh[(size_t)B_ROWS * IN_DIM];       // x fp16
__device__ __half g_wh[(size_t)NODE_PAD * IN_DIM];     // W^T fp16, [n][k]
__device__ __half g_vh[(size_t)OUT_DIM * N_LEAVES];    // value^T fp16, [n][k]
__device__ __half g_ph[(size_t)B_ROWS * N_LEAVES];     // leaf probs fp16
__device__ float  g_regpart[256 * NODE_PAD];

// ==========================================================================
// mma.sync fp16 helpers (sm_80-era PTX: valid on plain sm_103 target)
// ==========================================================================
__device__ __forceinline__ uint32_t smem_u32(const void* p) {
    uint32_t a;
    asm("{ .reg .u64 t; cvta.to.shared.u64 t, %1; cvt.u32.u64 %0, t; }" : "=r"(a) : "l"(p));
    return a;
}
#define LDSM_X4(r, a) \
    asm volatile("ldmatrix.sync.aligned.m8n8.x4.shared.b16 {%0,%1,%2,%3}, [%4];" \
        : "=r"((r)[0]), "=r"((r)[1]), "=r"((r)[2]), "=r"((r)[3]) : "r"(a))

__device__ __forceinline__ void mma_f16(float c[4], const uint32_t a[4],
                                        uint32_t b0, uint32_t b1) {
    asm volatile(
        "mma.sync.aligned.m16n8k16.row.col.f32.f16.f16.f32 "
        "{%0,%1,%2,%3}, {%4,%5,%6,%7}, {%8,%9}, {%0,%1,%2,%3};"
        : "+f"(c[0]), "+f"(c[1]), "+f"(c[2]), "+f"(c[3])
        : "r"(a[0]), "r"(a[1]), "r"(a[2]), "r"(a[3]), "r"(b0), "r"(b1));
}
#define CP_ASYNC16(s, g) \
    asm volatile("cp.async.cg.shared.global [%0], [%1], 16;" :: "r"(s), "l"(g))
#define CP_COMMIT()  asm volatile("cp.async.commit_group;")
#define CP_WAIT1()   asm volatile("cp.async.wait_group 1;")

// ==========================================================================
// fp16 single-product tensor-core GEMM: C = A@B^T
// A: [M][K] row-major fp16.  B: [n][K] k-major fp16.
// CTA tile 128x128, BK=32, 3-stage cp.async ring (2-tile prefetch depth,
// wait_group 1 + always-commit), one sync per k-tile, 8 warps (2x4),
// warp tile 64x32.  __launch_bounds__(256,2): 2 CTAs/SM (2x61440 smem).
// EPI==0: sigmoid(acc + bias[n]) -> fp32 C ; EPI==1: plain fp32 store
// ==========================================================================
#define ROWH   40            // smem row length in halves (32 data + 8 pad)
#define ROWB   80            // smem row stride bytes
#define MATB   (128 * ROWB)  // one matrix tile (128 rows) = 10240 B
#define STAGEB (2 * MATB)    // A, B per stage = 20480 B
#define NSTAGE 3
#define SMEM_DYN (NSTAGE * STAGEB)   // 61440 B

template <int EPI>
__global__ __launch_bounds__(256, 2)
void mma_gemm_kernel(const __half* __restrict__ Amat,
                     const __half* __restrict__ Bmat,
                     const float* __restrict__ bias,
                     float* __restrict__ Cout,
                     int K, int ldc, int Nvalid)
{
    extern __shared__ char smem[];
    const uint32_t sbase = smem_u32(smem);
    const int tid  = threadIdx.x;
    const int wid  = tid >> 5;
    const int lane = tid & 31;
    const int wm   = wid & 1;          // warp row  (2)  -> M 64
    const int wn   = wid >> 1;         // warp col  (4)  -> N 32

    const int row0 = blockIdx.y * 128;
    const int col0 = blockIdx.x * 128;

    const int T = K >> 5;              // k-tiles of 32

    // ---- cp.async mapping: 512 x 16B chunks per matrix, 2 per thread ----
    const int ch_r0  = tid >> 2;             // row of chunk 0   (0..63)
    const int ch_c0  = (tid & 3) << 3;       // half-offset 0/8/16/24

    // ---- ldmatrix per-lane offsets ----
    const int laA = ((lane & 15) * ROWH + ((lane >> 4) << 3)) * 2;  // A tiles
    const int laB = (((lane & 7) + ((lane >> 4) << 3)) * ROWH + (((lane >> 3) & 1) << 3)) * 2;

    float c[4][4][4];
    #pragma unroll
    for (int i = 0; i < 4; ++i)
        #pragma unroll
        for (int j = 0; j < 4; ++j)
            #pragma unroll
            for (int r = 0; r < 4; ++r) c[i][j][r] = 0.f;

    // ---- stage loader: A, B (2 matrices) ----
    auto load_stage = [&](int t, int s) {
        const uint32_t sb = sbase + s * STAGEB;
        const int kh = t * 32;                     // k offset in halves
        #pragma unroll
        for (int j = 0; j < 2; ++j) {              // A
            const int r = ch_r0 + j * 64;
            CP_ASYNC16(sb + r * ROWB + ch_c0 * 2,
                       Amat + (size_t)(row0 + r) * K + kh + ch_c0);
        }
        #pragma unroll
        for (int j = 0; j < 2; ++j) {              // B
            const int r = ch_r0 + j * 64;
            CP_ASYNC16(sb + MATB + r * ROWB + ch_c0 * 2,
                       Bmat + (size_t)(col0 + r) * K + kh + ch_c0);
        }
    };

    // ---- prologue: stages for tiles 0,1 ----
    load_stage(0, 0); CP_COMMIT();
    load_stage(1, 1); CP_COMMIT();

    int s_cur = 0;
    for (int t = 0; t < T; ++t) {
        // retire group carrying tile t (leaves tile t+1's group in flight)
        CP_WAIT1();
        __syncthreads();       // tile t visible to all; buffer (t+2)%3 free

        // prefetch t+2 (always commit so group accounting stays aligned)
        if (t + 2 < T) load_stage(t + 2, (s_cur + 2) % NSTAGE);
        CP_COMMIT();

        const uint32_t sb  = sbase + s_cur * STAGEB;
        const uint32_t aU  = sb;
        const uint32_t bU  = sb + MATB;

        #pragma unroll
        for (int ks = 0; ks < 2; ++ks) {
            const int ko = ks * 32;   // bytes: 16 halves
            uint32_t ah[4][4], bh[2][4];
            #pragma unroll
            for (int mi = 0; mi < 4; ++mi) {
                const uint32_t off = (wm * 64 + mi * 16) * ROWB + ko + laA;
                LDSM_X4(ah[mi], aU + off);
            }
            #pragma unroll
            for (int pr = 0; pr < 2; ++pr) {
                const uint32_t off = (wn * 32 + pr * 16) * ROWB + ko + laB;
                LDSM_X4(bh[pr], bU + off);
            }
            #pragma unroll
            for (int mi = 0; mi < 4; ++mi)
                #pragma unroll
                for (int ni = 0; ni < 4; ++ni) {
                    const int pr = ni >> 1, ix = (ni & 1) << 1;
                    mma_f16(c[mi][ni], ah[mi], bh[pr][ix], bh[pr][ix + 1]);
                }
        }
        s_cur = (s_cur + 1) % NSTAGE;
    }

    // ---- epilogue ----
    const int er = lane >> 2;            // 0..7
    const int ec = (lane & 3) << 1;      // 0,2,4,6
    #pragma unroll
    for (int mi = 0; mi < 4; ++mi) {
        #pragma unroll
        for (int ni = 0; ni < 4; ++ni) {
            const int gr = row0 + wm * 64 + mi * 16 + er;
            const int gc = col0 + wn * 32 + ni * 8 + ec;
            #pragma unroll
            for (int h = 0; h < 2; ++h) {          // row gr, gr+8
                float v0 = c[mi][ni][h * 2 + 0];
                float v1 = c[mi][ni][h * 2 + 1];
                if (EPI == 0) {
                    const float b0 = (gc + 0 < Nvalid) ? bias[gc + 0] : 0.f;
                    const float b1 = (gc + 1 < Nvalid) ? bias[gc + 1] : 0.f;
                    v0 = 1.f / (1.f + __expf(-(v0 + b0)));
                    v1 = 1.f / (1.f + __expf(-(v1 + b1)));
                }
                float2 st; st.x = v0; st.y = v1;
                *(float2*)&Cout[(size_t)(gr + h * 8) * ldc + gc] = st;
            }
        }
    }
}

// ==========================================================================
// x -> fp16 convert, vectorized
// ==========================================================================
__global__ __launch_bounds__(256)
void xconvert_kernel(const float* __restrict__ x, __half* __restrict__ hi)
{
    const size_t i4 = (size_t)blockIdx.x * 256 + threadIdx.x;   // float4 index
    const float4 v = ((const float4*)x)[i4];
    ((__half2*)hi)[i4 * 2 + 0] = __halves2half2(__float2half(v.x), __float2half(v.y));
    ((__half2*)hi)[i4 * 2 + 1] = __halves2half2(__float2half(v.z), __float2half(v.w));
}

// ==========================================================================
// transpose + fp16 convert:  src[R][Cv] (row-major) -> hi[Cpad][R] (k-major)
// ==========================================================================
__global__ __launch_bounds__(256)
void tsplit_kernel(const float* __restrict__ src,
                   __half* __restrict__ hi,
                   int R, int Cv)
{
    __shared__ float t[32][33];
    const int c0 = blockIdx.x * 32, r0 = blockIdx.y * 32;
    const int tx = threadIdx.x & 31, ty = threadIdx.x >> 5;
    #pragma unroll
    for (int i = 0; i < 4; ++i) {
        const int r = r0 + ty + i * 8, c = c0 + tx;
        t[ty + i * 8][tx] = (c < Cv) ? src[(size_t)r * Cv + c] : 0.f;
    }
    __syncthreads();
    #pragma unroll
    for (int i = 0; i < 4; ++i) {
        const int c = c0 + ty + i * 8, r = r0 + tx;
        hi[(size_t)c * R + r] = __float2half(t[tx][ty + i * 8]);
    }
}

// ==========================================================================
// Tree expansion: leaf probs (fp32 product) -> fp16
// ==========================================================================
__global__ __launch_bounds__(256)
void tree_kernel(const float* __restrict__ P, __half* __restrict__ ph)
{
    __shared__ float sP[NODE_PAD];
    const int row = blockIdx.x;
    const float* Prow = P + (size_t)row * NODE_PAD;
    for (int i = threadIdx.x; i < N_NODES; i += 256) sP[i] = Prow[i];
    __syncthreads();

    for (int lf = threadIdx.x; lf < N_LEAVES; lf += 256) {
        float prod = 1.f;
        #pragma unroll
        for (int d = 0; d < DEPTH; ++d) {
            const int idx  = lf >> (DEPTH - d);
            const int node = (1 << d) - 1 + idx;
            const float p  = sP[node];
            const int bit  = (lf >> (DEPTH - 1 - d)) & 1;
            prod *= bit ? (1.f - p) : p;
        }
        ph[(size_t)row * N_LEAVES + lf] = __float2half(prod);
    }
}

// ==========================================================================
// Regularizer (deterministic two-stage; 256 partial blocks x 64 rows)
// ==========================================================================
__global__ __launch_bounds__(256)
void reg_partial_kernel(const float* __restrict__ P, float* __restrict__ part)
{
    const int b  = blockIdx.x;        // 0..255
    const int c0 = threadIdx.x;
    float acc[4] = {0.f, 0.f, 0.f, 0.f};
    for (int r = 0; r < 64; ++r) {
        const float* Prow = P + (size_t)(b * 64 + r) * NODE_PAD;
        #pragma unroll
        for (int j = 0; j < 4; ++j) {
            const int c = c0 + j * 256;
            if (c < N_NODES) {
                const float p = Prow[c];
                acc[j] += __logf(fmaxf(p * (1.f - p), 1e-5f));
            }
        }
    }
    #pragma unroll
    for (int j = 0; j < 4; ++j) {
        const int c = c0 + j * 256;
        if (c < NODE_PAD) part[b * NODE_PAD + c] = (c < N_NODES) ? acc[j] : 0.f;
    }
}

__global__ __launch_bounds__(1024)
void reg_final_kernel(const float* __restrict__ part, float* __restrict__ out_reg)
{
    __shared__ float red[1024];
    const int c = threadIdx.x;
    float s = 0.f;
    if (c < N_NODES) {
        for (int i = 0; i < 256; ++i) s += part[i * NODE_PAD + c];
        const int d = 31 - __clz(c + 1);
        s = -0.5f * exp2f((float)(-d)) * (s / (float)B_ROWS);
    }
    red[c] = s;
    __syncthreads();
    #pragma unroll
    for (int st = 512; st > 0; st >>= 1) {
        if (c < st) red[c] += red[c + st];
        __syncthreads();
    }
    if (c == 0) *out_reg = red[0];
}

// ==========================================================================
extern "C" void kernel_launch(void* const* d_in, const int* in_sizes, int n_in,
                              void* d_out, int out_size)
{
    const float* x     = (const float*)d_in[0];   // [16384, 2048]
    const float* W     = (const float*)d_in[1];   // [2048, 1023]
    const float* bias  = (const float*)d_in[2];   // [1023]
    const float* value = (const float*)d_in[3];   // [1024, 512]
    float* out = (float*)d_out;

    float *P, *part;
    __half *xh, *wh, *vh, *ph;
    cudaGetSymbolAddress((void**)&P,  g_P);
    cudaGetSymbolAddress((void**)&part, g_regpart);
    cudaGetSymbolAddress((void**)&xh, g_xh);
    cudaGetSymbolAddress((void**)&wh, g_wh);
    cudaGetSymbolAddress((void**)&vh, g_vh);
    cudaGetSymbolAddress((void**)&ph, g_ph);

    cudaFuncSetAttribute(mma_gemm_kernel<0>, cudaFuncAttributeMaxDynamicSharedMemorySize, SMEM_DYN);
    cudaFuncSetAttribute(mma_gemm_kernel<1>, cudaFuncAttributeMaxDynamicSharedMemorySize, SMEM_DYN);

    // 1. operand converts
    xconvert_kernel<<<(B_ROWS * IN_DIM) / 1024, 256>>>(x, xh);
    {   // W [2048,1023] -> wh [1024][2048]
        dim3 g(NODE_PAD / 32, IN_DIM / 32);
        tsplit_kernel<<<g, 256>>>(W, wh, IN_DIM, N_NODES);
    }
    {   // value [1024,512] -> vh [512][1024]
        dim3 g(OUT_DIM / 32, N_LEAVES / 32);
        tsplit_kernel<<<g, 256>>>(value, vh, N_LEAVES, OUT_DIM);
    }

    // 2. GEMM1: P = sigmoid(x@W + b)   M=16384, N=1024(pad), K=2048
    {
        dim3 grid(NODE_PAD / 128, B_ROWS / 128);   // (8, 128)
        mma_gemm_kernel<0><<<grid, 256, SMEM_DYN>>>(xh, wh, bias, P,
                                                    IN_DIM, NODE_PAD, N_NODES);
    }

    // 3. tree -> leaf probs (fp16)
    tree_kernel<<<B_ROWS, 256>>>(P, ph);

    // 4. regularizer
    reg_partial_kernel<<<256, 256>>>(P, part);
    if (out_size > B_ROWS * OUT_DIM) {
        reg_final_kernel<<<1, 1024>>>(part, out + (out_size - 1));
    }

    // 5. GEMM2: out = probs @ value   M=16384, N=512, K=1024
    {
        dim3 grid(OUT_DIM / 128, B_ROWS / 128);    // (4, 128)
        mma_gemm_kernel<1><<<grid, 256, SMEM_DYN>>>(ph, vh, nullptr, out,
                                                    N_LEAVES, OUT_DIM, OUT_DIM);
    }
}

// round 17
// speedup vs baseline: 2.2197x; 1.0482x over previous
#include <cuda_runtime.h>
#include <cuda_fp16.h>
#include <math.h>
#include <stdint.h>

// ---------------- problem constants ----------------
#define B_ROWS   16384
#define IN_DIM   2048
#define N_NODES  1023
#define NODE_PAD 1024
#define N_LEAVES 1024
#define OUT_DIM  512
#define DEPTH    10

// ---------------- device scratch (no allocations allowed) ----------------
__device__ float  g_P [(size_t)B_ROWS * NODE_PAD];     // fp32 node probs
__device__ __half g_xh[(size_t)B_ROWS * IN_DIM];       // x fp16
__device__ __half g_wh[(size_t)NODE_PAD * IN_DIM];     // W^T fp16, [n][k]
__device__ __half g_vh[(size_t)OUT_DIM * N_LEAVES];    // value^T fp16, [n][k]
__device__ __half g_ph[(size_t)B_ROWS * N_LEAVES];     // leaf probs fp16
__device__ float  g_regpart[256 * NODE_PAD];

// ==========================================================================
// mma.sync fp16 helpers (sm_80-era PTX: valid on plain sm_103 target)
// ==========================================================================
__device__ __forceinline__ uint32_t smem_u32(const void* p) {
    uint32_t a;
    asm("{ .reg .u64 t; cvta.to.shared.u64 t, %1; cvt.u32.u64 %0, t; }" : "=r"(a) : "l"(p));
    return a;
}
#define LDSM_X4(r, a) \
    asm volatile("ldmatrix.sync.aligned.m8n8.x4.shared.b16 {%0,%1,%2,%3}, [%4];" \
        : "=r"((r)[0]), "=r"((r)[1]), "=r"((r)[2]), "=r"((r)[3]) : "r"(a))

__device__ __forceinline__ void mma_f16(float c[4], const uint32_t a[4],
                                        uint32_t b0, uint32_t b1) {
    asm volatile(
        "mma.sync.aligned.m16n8k16.row.col.f32.f16.f16.f32 "
        "{%0,%1,%2,%3}, {%4,%5,%6,%7}, {%8,%9}, {%0,%1,%2,%3};"
        : "+f"(c[0]), "+f"(c[1]), "+f"(c[2]), "+f"(c[3])
        : "r"(a[0]), "r"(a[1]), "r"(a[2]), "r"(a[3]), "r"(b0), "r"(b1));
}
#define CP_ASYNC16(s, g) \
    asm volatile("cp.async.cg.shared.global [%0], [%1], 16;" :: "r"(s), "l"(g))
#define CP_COMMIT()  asm volatile("cp.async.commit_group;")
#define CP_WAIT0()   asm volatile("cp.async.wait_group 0;")

// ==========================================================================
// fp16 single-product tensor-core GEMM: C = A@B^T
// A: [M][K] row-major fp16.  B: [n][K] k-major fp16.
// CTA tile 128x128, BK=64 (fat k-tiles amortize per-tile barrier/wait/loop
// overhead: 64 HMMA per warp per tile), 2-stage double buffer, one sync per
// k-tile, 8 warps (2x4), warp tile 64x32.
// __launch_bounds__(256,2): 2 CTAs/SM (2x73728 smem = 147KB < 227KB).
// EPI==0: sigmoid(acc + bias[n]) -> fp32 C ; EPI==1: plain fp32 store
// ==========================================================================
#define ROWH   72            // smem row length in halves (64 data + 8 pad)
#define ROWB   144           // smem row stride bytes (16B-mod-128 shift: conflict-free)
#define MATB   (128 * ROWB)  // one matrix tile (128 rows) = 18432 B
#define STAGEB (2 * MATB)    // A, B per stage = 36864 B
#define NSTAGE 2
#define SMEM_DYN (NSTAGE * STAGEB)   // 73728 B

template <int EPI>
__global__ __launch_bounds__(256, 2)
void mma_gemm_kernel(const __half* __restrict__ Amat,
                     const __half* __restrict__ Bmat,
                     const float* __restrict__ bias,
                     float* __restrict__ Cout,
                     int K, int ldc, int Nvalid)
{
    extern __shared__ char smem[];
    const uint32_t sbase = smem_u32(smem);
    const int tid  = threadIdx.x;
    const int wid  = tid >> 5;
    const int lane = tid & 31;
    const int wm   = wid & 1;          // warp row  (2)  -> M 64
    const int wn   = wid >> 1;         // warp col  (4)  -> N 32

    const int row0 = blockIdx.y * 128;
    const int col0 = blockIdx.x * 128;

    const int T = K >> 6;              // k-tiles of 64

    // ---- cp.async mapping: 1024 x 16B chunks per matrix, 4 per thread ----
    const int ch_r0  = tid >> 3;             // row of chunk 0   (0..31)
    const int ch_c0  = (tid & 7) << 3;       // half-offset 0..56

    // ---- ldmatrix per-lane offsets ----
    const int laA = ((lane & 15) * ROWH + ((lane >> 4) << 3)) * 2;  // A tiles
    const int laB = (((lane & 7) + ((lane >> 4) << 3)) * ROWH + (((lane >> 3) & 1) << 3)) * 2;

    float c[4][4][4];
    #pragma unroll
    for (int i = 0; i < 4; ++i)
        #pragma unroll
        for (int j = 0; j < 4; ++j)
            #pragma unroll
            for (int r = 0; r < 4; ++r) c[i][j][r] = 0.f;

    // ---- stage loader: A, B (2 matrices, 128 rows x 64 halves each) ----
    auto load_stage = [&](int t, int s) {
        const uint32_t sb = sbase + s * STAGEB;
        const int kh = t * 64;                     // k offset in halves
        #pragma unroll
        for (int j = 0; j < 4; ++j) {              // A
            const int r = ch_r0 + j * 32;
            CP_ASYNC16(sb + r * ROWB + ch_c0 * 2,
                       Amat + (size_t)(row0 + r) * K + kh + ch_c0);
        }
        #pragma unroll
        for (int j = 0; j < 4; ++j) {              // B
            const int r = ch_r0 + j * 32;
            CP_ASYNC16(sb + MATB + r * ROWB + ch_c0 * 2,
                       Bmat + (size_t)(col0 + r) * K + kh + ch_c0);
        }
    };

    // ---- prologue: stage 0 ----
    load_stage(0, 0); CP_COMMIT();

    for (int t = 0; t < T; ++t) {
        const int cur = t & 1;

        CP_WAIT0();
        __syncthreads();       // single barrier: data ready AND buffer cur^1 free

        if (t + 1 < T) { load_stage(t + 1, cur ^ 1); CP_COMMIT(); }

        const uint32_t sb  = sbase + cur * STAGEB;
        const uint32_t aU  = sb;
        const uint32_t bU  = sb + MATB;

        #pragma unroll
        for (int ks = 0; ks < 4; ++ks) {
            const int ko = ks * 32;   // bytes: 16 halves
            uint32_t ah[4][4], bh[2][4];
            #pragma unroll
            for (int mi = 0; mi < 4; ++mi) {
                const uint32_t off = (wm * 64 + mi * 16) * ROWB + ko + laA;
                LDSM_X4(ah[mi], aU + off);
            }
            #pragma unroll
            for (int pr = 0; pr < 2; ++pr) {
                const uint32_t off = (wn * 32 + pr * 16) * ROWB + ko + laB;
                LDSM_X4(bh[pr], bU + off);
            }
            #pragma unroll
            for (int mi = 0; mi < 4; ++mi)
                #pragma unroll
                for (int ni = 0; ni < 4; ++ni) {
                    const int pr = ni >> 1, ix = (ni & 1) << 1;
                    mma_f16(c[mi][ni], ah[mi], bh[pr][ix], bh[pr][ix + 1]);
                }
        }
    }

    // ---- epilogue ----
    const int er = lane >> 2;            // 0..7
    const int ec = (lane & 3) << 1;      // 0,2,4,6
    #pragma unroll
    for (int mi = 0; mi < 4; ++mi) {
        #pragma unroll
        for (int ni = 0; ni < 4; ++ni) {
            const int gr = row0 + wm * 64 + mi * 16 + er;
            const int gc = col0 + wn * 32 + ni * 8 + ec;
            #pragma unroll
            for (int h = 0; h < 2; ++h) {          // row gr, gr+8
                float v0 = c[mi][ni][h * 2 + 0];
                float v1 = c[mi][ni][h * 2 + 1];
                if (EPI == 0) {
                    const float b0 = (gc + 0 < Nvalid) ? bias[gc + 0] : 0.f;
                    const float b1 = (gc + 1 < Nvalid) ? bias[gc + 1] : 0.f;
                    v0 = 1.f / (1.f + __expf(-(v0 + b0)));
                    v1 = 1.f / (1.f + __expf(-(v1 + b1)));
                }
                float2 st; st.x = v0; st.y = v1;
                *(float2*)&Cout[(size_t)(gr + h * 8) * ldc + gc] = st;
            }
        }
    }
}

// ==========================================================================
// x -> fp16 convert, vectorized
// ==========================================================================
__global__ __launch_bounds__(256)
void xconvert_kernel(const float* __restrict__ x, __half* __restrict__ hi)
{
    const size_t i4 = (size_t)blockIdx.x * 256 + threadIdx.x;   // float4 index
    const float4 v = ((const float4*)x)[i4];
    ((__half2*)hi)[i4 * 2 + 0] = __halves2half2(__float2half(v.x), __float2half(v.y));
    ((__half2*)hi)[i4 * 2 + 1] = __halves2half2(__float2half(v.z), __float2half(v.w));
}

// ==========================================================================
// transpose + fp16 convert:  src[R][Cv] (row-major) -> hi[Cpad][R] (k-major)
// ==========================================================================
__global__ __launch_bounds__(256)
void tsplit_kernel(const float* __restrict__ src,
                   __half* __restrict__ hi,
                   int R, int Cv)
{
    __shared__ float t[32][33];
    const int c0 = blockIdx.x * 32, r0 = blockIdx.y * 32;
    const int tx = threadIdx.x & 31, ty = threadIdx.x >> 5;
    #pragma unroll
    for (int i = 0; i < 4; ++i) {
        const int r = r0 + ty + i * 8, c = c0 + tx;
        t[ty + i * 8][tx] = (c < Cv) ? src[(size_t)r * Cv + c] : 0.f;
    }
    __syncthreads();
    #pragma unroll
    for (int i = 0; i < 4; ++i) {
        const int c = c0 + ty + i * 8, r = r0 + tx;
        hi[(size_t)c * R + r] = __float2half(t[tx][ty + i * 8]);
    }
}

// ==========================================================================
// Tree expansion: leaf probs (fp32 product) -> fp16
// ==========================================================================
__global__ __launch_bounds__(256)
void tree_kernel(const float* __restrict__ P, __half* __restrict__ ph)
{
    __shared__ float sP[NODE_PAD];
    const int row = blockIdx.x;
    const float* Prow = P + (size_t)row * NODE_PAD;
    for (int i = threadIdx.x; i < N_NODES; i += 256) sP[i] = Prow[i];
    __syncthreads();

    for (int lf = threadIdx.x; lf < N_LEAVES; lf += 256) {
        float prod = 1.f;
        #pragma unroll
        for (int d = 0; d < DEPTH; ++d) {
            const int idx  = lf >> (DEPTH - d);
            const int node = (1 << d) - 1 + idx;
            const float p  = sP[node];
            const int bit  = (lf >> (DEPTH - 1 - d)) & 1;
            prod *= bit ? (1.f - p) : p;
        }
        ph[(size_t)row * N_LEAVES + lf] = __float2half(prod);
    }
}

// ==========================================================================
// Regularizer stage 1 (256 blocks x 64 rows): log-of-products batching.
// sum_r log(term_r) == sum over batches of log(prod of 4 terms); terms in
// [1e-5, 0.25] so a 4-term product >= 1e-20 (no underflow). 4x fewer MUFU.
// ==========================================================================
__global__ __launch_bounds__(256)
void reg_partial_kernel(const float* __restrict__ P, float* __restrict__ part)
{
    const int b  = blockIdx.x;        // 0..255
    const int c0 = threadIdx.x;
    float acc[4] = {0.f, 0.f, 0.f, 0.f};
    float pr[4]  = {1.f, 1.f, 1.f, 1.f};
    for (int r = 0; r < 64; ++r) {
        const float* Prow = P + (size_t)(b * 64 + r) * NODE_PAD;
        #pragma unroll
        for (int j = 0; j < 4; ++j) {
            const int c = c0 + j * 256;
            if (c < N_NODES) {
                const float p = Prow[c];
                pr[j] *= fmaxf(p * (1.f - p), 1e-5f);
            }
        }
        if ((r & 3) == 3) {
            #pragma unroll
            for (int j = 0; j < 4; ++j) { acc[j] += __logf(pr[j]); pr[j] = 1.f; }
        }
    }
    #pragma unroll
    for (int j = 0; j < 4; ++j) {
        const int c = c0 + j * 256;
        if (c < NODE_PAD) part[b * NODE_PAD + c] = (c < N_NODES) ? acc[j] : 0.f;
    }
}

__global__ __launch_bounds__(1024)
void reg_final_kernel(const float* __restrict__ part, float* __restrict__ out_reg)
{
    __shared__ float red[1024];
    const int c = threadIdx.x;
    float s = 0.f;
    if (c < N_NODES) {
        for (int i = 0; i < 256; ++i) s += part[i * NODE_PAD + c];
        const int d = 31 - __clz(c + 1);
        s = -0.5f * exp2f((float)(-d)) * (s / (float)B_ROWS);
    }
    red[c] = s;
    __syncthreads();
    #pragma unroll
    for (int st = 512; st > 0; st >>= 1) {
        if (c < st) red[c] += red[c + st];
        __syncthreads();
    }
    if (c == 0) *out_reg = red[0];
}

// ==========================================================================
extern "C" void kernel_launch(void* const* d_in, const int* in_sizes, int n_in,
                              void* d_out, int out_size)
{
    const float* x     = (const float*)d_in[0];   // [16384, 2048]
    const float* W     = (const float*)d_in[1];   // [2048, 1023]
    const float* bias  = (const float*)d_in[2];   // [1023]
    const float* value = (const float*)d_in[3];   // [1024, 512]
    float* out = (float*)d_out;

    float *P, *part;
    __half *xh, *wh, *vh, *ph;
    cudaGetSymbolAddress((void**)&P,  g_P);
    cudaGetSymbolAddress((void**)&part, g_regpart);
    cudaGetSymbolAddress((void**)&xh, g_xh);
    cudaGetSymbolAddress((void**)&wh, g_wh);
    cudaGetSymbolAddress((void**)&vh, g_vh);
    cudaGetSymbolAddress((void**)&ph, g_ph);

    cudaFuncSetAttribute(mma_gemm_kernel<0>, cudaFuncAttributeMaxDynamicSharedMemorySize, SMEM_DYN);
    cudaFuncSetAttribute(mma_gemm_kernel<1>, cudaFuncAttributeMaxDynamicSharedMemorySize, SMEM_DYN);

    // 1. operand converts
    xconvert_kernel<<<(B_ROWS * IN_DIM) / 1024, 256>>>(x, xh);
    {   // W [2048,1023] -> wh [1024][2048]
        dim3 g(NODE_PAD / 32, IN_DIM / 32);
        tsplit_kernel<<<g, 256>>>(W, wh, IN_DIM, N_NODES);
    }
    {   // value [1024,512] -> vh [512][1024]
        dim3 g(OUT_DIM / 32, N_LEAVES / 32);
        tsplit_kernel<<<g, 256>>>(value, vh, N_LEAVES, OUT_DIM);
    }

    // 2. GEMM1: P = sigmoid(x@W + b)   M=16384, N=1024(pad), K=2048
    {
        dim3 grid(NODE_PAD / 128, B_ROWS / 128);   // (8, 128)
        mma_gemm_kernel<0><<<grid, 256, SMEM_DYN>>>(xh, wh, bias, P,
                                                    IN_DIM, NODE_PAD, N_NODES);
    }

    // 3. tree -> leaf probs (fp16)
    tree_kernel<<<B_ROWS, 256>>>(P, ph);

    // 4. regularizer
    reg_partial_kernel<<<256, 256>>>(P, part);
    if (out_size > B_ROWS * OUT_DIM) {
        reg_final_kernel<<<1, 1024>>>(part, out + (out_size - 1));
    }

    // 5. GEMM2: out = probs @ value   M=16384, N=512, K=1024
    {
        dim3 grid(OUT_DIM / 128, B_ROWS / 128);    // (4, 128)
        mma_gemm_kernel<1><<<grid, 256, SMEM_DYN>>>(ph, vh, nullptr, out,
                                                    N_LEAVES, OUT_DIM, OUT_DIM);
    }
}